// round 12
// baseline (speedup 1.0000x reference)
#include <cuda_runtime.h>
#include <cuda_fp16.h>
#include <math.h>
#include <stdint.h>

#define Bdim 8
#define Ndim 256
#define Ddim 128
#define K2   256

// Projections stored as fp16 (allocation-free rule -> device globals)
__device__ __half g_Pi[Bdim * Ndim * K2];   // includes b1
__device__ __half g_Pj[Bdim * Ndim * K2];
__device__ int    g_ctr;                    // work-stealing tile counter

// ---------------------------------------------------------------------------
// common helpers
// ---------------------------------------------------------------------------
__device__ __forceinline__ void mma_f16(float* d, const uint32_t* a,
                                        uint32_t b0, uint32_t b1) {
    asm volatile(
        "mma.sync.aligned.m16n8k16.row.col.f32.f16.f16.f32 "
        "{%0,%1,%2,%3},{%4,%5,%6,%7},{%8,%9},{%0,%1,%2,%3};\n"
        : "+f"(d[0]), "+f"(d[1]), "+f"(d[2]), "+f"(d[3])
        : "r"(a[0]), "r"(a[1]), "r"(a[2]), "r"(a[3]), "r"(b0), "r"(b1));
}
__device__ __forceinline__ void cpa16(uint32_t dst, const void* src) {
    asm volatile("cp.async.ca.shared.global [%0], [%1], 16;"
                 :: "r"(dst), "l"(src) : "memory");
}
__device__ __forceinline__ uint32_t smem_u32(const void* p) {
    uint32_t a;
    asm("{ .reg .u64 t; cvta.to.shared.u64 t, %1; cvt.u32.u64 %0, t; }"
        : "=r"(a) : "l"(p));
    return a;
}
__device__ __forceinline__ uint32_t packh2(float a, float b) {
    __half2 h = __floats2half2_rn(a, b);
    return *(uint32_t*)&h;
}
__device__ __forceinline__ uint32_t h2u(__half2 h) { return *(uint32_t*)&h; }

// ===========================================================================
// Kernel 1: proj as fp16 tensor GEMM (R9, proven).
// ===========================================================================
#define PA_STR 264
#define PW_OFF_B 0
#define PA_OFF_B 65536
#define PB1_OFF_B (PA_OFF_B + 33792)
#define SMEM_BYTES_PROJ (PB1_OFF_B + 1024)

__global__ void __launch_bounds__(256, 1) proj_mma_kernel(
    const float* __restrict__ x, const float* __restrict__ W1,
    const float* __restrict__ b1, float* __restrict__ outTour, int hasTour)
{
    extern __shared__ char smc[];
    float4* sW4 = (float4*)(smc + PW_OFF_B);
    __half* sA  = (__half*)(smc + PA_OFF_B);
    float*  sb1 = (float*)(smc + PB1_OFF_B);

    const int tid  = threadIdx.x;
    const int wid  = tid >> 5;
    const int lane = tid & 31;
    const int q = lane >> 2;
    const int c = lane & 3;
    const int nb = blockIdx.x * 128;
    const int n0 = blockIdx.y * 64;
    const int b  = blockIdx.z;

    for (int idx = tid; idx < 4096; idx += 256) {
        int ln  = idx & 31;
        int wn4 = (idx >> 5) & 3;
        int gg  = (idx >> 7) & 1;
        int s   = idx >> 8;
        int cc = ln & 3, qq = ln >> 2;
        int k0 = 16 * s + 2 * cc;
        int nA = nb + wn4 * 32 + (2 * gg) * 8 + qq;
        int nB = nA + 8;
        const float* WA = (nA < 256) ? (W1 + nA) : (W1 + 256 * 256 + (nA - 256));
        const float* WB = (nB < 256) ? (W1 + nB) : (W1 + 256 * 256 + (nB - 256));
        float4 v;
        v.x = __uint_as_float(packh2(WA[k0 * 256],       WA[(k0 + 1) * 256]));
        v.y = __uint_as_float(packh2(WA[(k0 + 8) * 256], WA[(k0 + 9) * 256]));
        v.z = __uint_as_float(packh2(WB[k0 * 256],       WB[(k0 + 1) * 256]));
        v.w = __uint_as_float(packh2(WB[(k0 + 8) * 256], WB[(k0 + 9) * 256]));
        sW4[idx] = v;
    }
    if (tid < 256) sb1[tid] = b1[tid];

    for (int idx = tid; idx < 16384; idx += 256) {
        int m = idx >> 8, k = idx & 255;
        float v = (k < 128)
            ? x[((b << 8) + n0 + m) * 128 + k]
            : x[((b << 8) + ((n0 + m + 1) & 255)) * 128 + (k - 128)];
        sA[m * PA_STR + k] = __float2half(v);
    }
    __syncthreads();

    const int wm  = wid >> 2;
    const int wn4 = wid & 3;
    const float4* myW = sW4 + wn4 * 32 + lane;

    float acc[2][4][4];
#pragma unroll
    for (int am = 0; am < 2; am++)
#pragma unroll
        for (int a = 0; a < 4; a++)
#pragma unroll
            for (int e = 0; e < 4; e++) acc[am][a][e] = 0.f;

#pragma unroll 4
    for (int s = 0; s < 16; s++) {
        const int k0 = 16 * s + 2 * c;
        float4 f0 = myW[(s * 2 + 0) * 128];
        float4 f1 = myW[(s * 2 + 1) * 128];
        uint32_t bf[4][2];
        bf[0][0] = __float_as_uint(f0.x); bf[0][1] = __float_as_uint(f0.y);
        bf[1][0] = __float_as_uint(f0.z); bf[1][1] = __float_as_uint(f0.w);
        bf[2][0] = __float_as_uint(f1.x); bf[2][1] = __float_as_uint(f1.y);
        bf[3][0] = __float_as_uint(f1.z); bf[3][1] = __float_as_uint(f1.w);
#pragma unroll
        for (int am = 0; am < 2; am++) {
            const int base = wm * 32 + am * 16;
            uint32_t af[4];
            af[0] = *(const uint32_t*)(sA + (base + q) * PA_STR + k0);
            af[1] = *(const uint32_t*)(sA + (base + q + 8) * PA_STR + k0);
            af[2] = *(const uint32_t*)(sA + (base + q) * PA_STR + k0 + 8);
            af[3] = *(const uint32_t*)(sA + (base + q + 8) * PA_STR + k0 + 8);
#pragma unroll
            for (int a = 0; a < 4; a++) mma_f16(acc[am][a], af, bf[a][0], bf[a][1]);
        }
    }

#pragma unroll
    for (int am = 0; am < 2; am++) {
#pragma unroll
        for (int a = 0; a < 4; a++) {
            int col0 = nb + wn4 * 32 + a * 8 + 2 * c;
            int r0 = wm * 32 + am * 16 + q;
            float e0 = acc[am][a][0], e1 = acc[am][a][1];
            float e2 = acc[am][a][2], e3 = acc[am][a][3];
            if (col0 < 256) {
                float bb0 = sb1[col0], bb1 = sb1[col0 + 1];
                uint32_t* d0 = (uint32_t*)(g_Pi + ((b << 8) + n0 + r0) * 256 + col0);
                uint32_t* d1 = (uint32_t*)(g_Pi + ((b << 8) + n0 + r0 + 8) * 256 + col0);
                *d0 = packh2(e0 + bb0, e1 + bb1);
                *d1 = packh2(e2 + bb0, e3 + bb1);
            } else {
                int cj = col0 - 256;
                uint32_t* d0 = (uint32_t*)(g_Pj + ((b << 8) + n0 + r0) * 256 + cj);
                uint32_t* d1 = (uint32_t*)(g_Pj + ((b << 8) + n0 + r0 + 8) * 256 + cj);
                *d0 = packh2(e0, e1);
                *d1 = packh2(e2, e3);
            }
        }
    }
    if (hasTour && blockIdx.x == 0 && tid < 64)
        outTour[b * Ndim + n0 + tid] = (float)(n0 + tid);
}

// ===========================================================================
// Kernel 2: fp16 pair kernel (R11 loop) + atomic work-stealing tile queue.
// 256 threads / 8 warps, tile M=128 (16i x 8j) x N=128, K=256, 2 CTAs/SM.
// ===========================================================================
#define PIS_H 264
#define OFF_W2F_B 0                         // packed fp16 B frags: 65536 B
#define OFF_PI0_B 65536                     // 16*528 = 8448
#define OFF_PI1_B (OFF_PI0_B + 8448)        // 73984
#define OFF_PJ0_B (OFF_PI1_B + 8448)        // 82432 ; 8*528 = 4224
#define OFF_PJ1_B (OFF_PJ0_B + 4224)        // 86656
#define OFF_B2_B  (OFF_PJ1_B + 4224)        // 90880
#define OFF_W3_B  (OFF_B2_B + 512)          // 91392
#define OFF_RED_B (OFF_W3_B + 512)          // 91904 ; 256 floats = 1024 B
#define OFF_IDX_B (OFF_RED_B + 1024)        // 92928 ; next-tile broadcast
#define SMEM_BYTES_PAIR (OFF_IDX_B + 16)    // 92944

#define NTILES_PER_B 272                    // sum_{bi=0..15} (32 - 2*bi)
#define NTILES_TOT   (Bdim * NTILES_PER_B)  // 2176
#define GRID_PAIR    304
#define NTHREADS     256

__device__ __forceinline__ void tile_coords(int t, int& b, int& i0, int& j0) {
    b = t / NTILES_PER_B;
    int r = t - b * NTILES_PER_B;
    int bi = 0;
    while (r >= 32 - 2 * bi) { r -= 32 - 2 * bi; bi++; }
    i0 = bi * 16;
    j0 = (2 * bi + r) * 8;
}

__global__ void __launch_bounds__(NTHREADS, 2) pair_mma_kernel(
    const float* __restrict__ W2g, const float* __restrict__ b2g,
    const float* __restrict__ W3g, const float* __restrict__ b3g,
    float* __restrict__ outM)
{
    extern __shared__ char smc[];
    float4* sW2f4 = (float4*)(smc + OFF_W2F_B);
    float* sB2  = (float*)(smc + OFF_B2_B);
    float* sW3  = (float*)(smc + OFF_W3_B);
    float* sRed = (float*)(smc + OFF_RED_B);
    int*   sIdx = (int*)(smc + OFF_IDX_B);
    const uint32_t sbase = smem_u32(smc);

    const int tid  = threadIdx.x;
    const int wid  = tid >> 5;
    const int lane = tid & 31;
    const int q = lane >> 2;
    const int c = lane & 3;

    // pack fp16 B fragments (R9 layout): float4 idx ((s*4+g)*2+wn)*32+lane
    for (int idx = tid; idx < 4096; idx += NTHREADS) {
        int ln  = idx & 31;
        int wnn = (idx >> 5) & 1;
        int g   = (idx >> 6) & 3;
        int s   = idx >> 8;
        int cc  = ln & 3, qq = ln >> 2;
        int k0  = 16 * s + 2 * cc;
        int n0  = 64 * wnn + 16 * g + qq;
        int n1  = n0 + 8;
        float4 v;
        v.x = __uint_as_float(packh2(W2g[k0 * 128 + n0],       W2g[(k0 + 1) * 128 + n0]));
        v.y = __uint_as_float(packh2(W2g[(k0 + 8) * 128 + n0], W2g[(k0 + 9) * 128 + n0]));
        v.z = __uint_as_float(packh2(W2g[k0 * 128 + n1],       W2g[(k0 + 1) * 128 + n1]));
        v.w = __uint_as_float(packh2(W2g[(k0 + 8) * 128 + n1], W2g[(k0 + 9) * 128 + n1]));
        sW2f4[idx] = v;
    }
    if (tid < 128) { sB2[tid] = b2g[tid]; sW3[tid] = W3g[tid]; }
    const float b3v = b3g[0];

    const int wm = wid >> 1;
    const int wn = wid & 1;
    const int mb = wm * 32;
    const int nb = wn * 64;
    const float4* myB = sW2f4 + wn * 32 + lane;

    // grab first tile + prefetch into buffer 0
    if (tid == 0) sIdx[0] = atomicAdd(&g_ctr, 1);
    __syncthreads();
    int cur = sIdx[0];
    if (cur < NTILES_TOT) {
        int b, i0, j0;
        tile_coords(cur, b, i0, j0);
        const __half* gPi = g_Pi + (size_t)(b * Ndim + i0) * K2;
        const __half* gPj = g_Pj + (size_t)(b * Ndim + j0) * K2;
#pragma unroll
        for (int u = 0; u < 2; u++) {
            int idx = u * NTHREADS + tid;
            int row = idx >> 5, ch = idx & 31;
            cpa16(sbase + OFF_PI0_B + row * 528 + ch * 16, gPi + row * 256 + ch * 8);
        }
        {
            int row = tid >> 5, ch = tid & 31;
            cpa16(sbase + OFF_PJ0_B + row * 528 + ch * 16, gPj + row * 256 + ch * 8);
        }
    }
    asm volatile("cp.async.commit_group;" ::: "memory");

    const __half2 hz = __float2half2_rn(0.f);
    int buf = 0;

    while (cur < NTILES_TOT) {
        // grab + prefetch next tile into the other buffer
        if (tid == 0) sIdx[0] = atomicAdd(&g_ctr, 1);
        __syncthreads();   // sIdx visible; prior reads of buf^1 complete
        const int next = sIdx[0];
        if (next < NTILES_TOT) {
            int b, i0, j0;
            tile_coords(next, b, i0, j0);
            const __half* gPi = g_Pi + (size_t)(b * Ndim + i0) * K2;
            const __half* gPj = g_Pj + (size_t)(b * Ndim + j0) * K2;
            const int piO = buf ? OFF_PI0_B : OFF_PI1_B;
            const int pjO = buf ? OFF_PJ0_B : OFF_PJ1_B;
#pragma unroll
            for (int u = 0; u < 2; u++) {
                int idx = u * NTHREADS + tid;
                int row = idx >> 5, ch = idx & 31;
                cpa16(sbase + piO + row * 528 + ch * 16, gPi + row * 256 + ch * 8);
            }
            {
                int row = tid >> 5, ch = tid & 31;
                cpa16(sbase + pjO + row * 528 + ch * 16, gPj + row * 256 + ch * 8);
            }
        }
        asm volatile("cp.async.commit_group;" ::: "memory");
        asm volatile("cp.async.wait_group 1;" ::: "memory");
        __syncthreads();   // current tile's data visible to all threads

        int b, i0, j0;
        tile_coords(cur, b, i0, j0);

        const __half* sPi = (const __half*)(smc + (buf ? OFF_PI1_B : OFF_PI0_B));
        const __half* sPj = (const __half*)(smc + (buf ? OFF_PJ1_B : OFF_PJ0_B));
        const __half* piR0 = sPi + ((mb >> 3) + 0) * PIS_H;
        const __half* piR1 = sPi + ((mb >> 3) + 1) * PIS_H;
        const __half* piR2 = sPi + ((mb >> 3) + 2) * PIS_H;
        const __half* piR3 = sPi + ((mb >> 3) + 3) * PIS_H;
        const __half* pjR  = sPj + q * PIS_H;

        float acc[2][8][4];
#pragma unroll
        for (int am = 0; am < 2; am++)
#pragma unroll
            for (int a = 0; a < 8; a++)
#pragma unroll
                for (int e = 0; e < 4; e++) acc[am][a][e] = 0.f;

#pragma unroll 4
        for (int s = 0; s < 16; s++) {
            const int k0 = 16 * s + 2 * c;
            const int k8 = k0 + 8;

            float4 f0 = myB[(s * 4 + 0) * 64];
            float4 f1 = myB[(s * 4 + 1) * 64];
            float4 f2 = myB[(s * 4 + 2) * 64];
            float4 f3 = myB[(s * 4 + 3) * 64];
            uint32_t bf[8][2];
            bf[0][0] = __float_as_uint(f0.x); bf[0][1] = __float_as_uint(f0.y);
            bf[1][0] = __float_as_uint(f0.z); bf[1][1] = __float_as_uint(f0.w);
            bf[2][0] = __float_as_uint(f1.x); bf[2][1] = __float_as_uint(f1.y);
            bf[3][0] = __float_as_uint(f1.z); bf[3][1] = __float_as_uint(f1.w);
            bf[4][0] = __float_as_uint(f2.x); bf[4][1] = __float_as_uint(f2.y);
            bf[5][0] = __float_as_uint(f2.z); bf[5][1] = __float_as_uint(f2.w);
            bf[6][0] = __float_as_uint(f3.x); bf[6][1] = __float_as_uint(f3.y);
            bf[7][0] = __float_as_uint(f3.z); bf[7][1] = __float_as_uint(f3.w);

            const __half2 pj0 = *(const __half2*)(pjR + k0);
            const __half2 pj1 = *(const __half2*)(pjR + k8);

            {   // M-atom 0: rows mb+q, mb+q+8
                uint32_t af[4];
                af[0] = h2u(__hmax2(__hadd2(*(const __half2*)(piR0 + k0), pj0), hz));
                af[1] = h2u(__hmax2(__hadd2(*(const __half2*)(piR1 + k0), pj0), hz));
                af[2] = h2u(__hmax2(__hadd2(*(const __half2*)(piR0 + k8), pj1), hz));
                af[3] = h2u(__hmax2(__hadd2(*(const __half2*)(piR1 + k8), pj1), hz));
#pragma unroll
                for (int a = 0; a < 8; a++) mma_f16(acc[0][a], af, bf[a][0], bf[a][1]);
            }
            {   // M-atom 1: rows mb+q+16, mb+q+24
                uint32_t af[4];
                af[0] = h2u(__hmax2(__hadd2(*(const __half2*)(piR2 + k0), pj0), hz));
                af[1] = h2u(__hmax2(__hadd2(*(const __half2*)(piR3 + k0), pj0), hz));
                af[2] = h2u(__hmax2(__hadd2(*(const __half2*)(piR2 + k8), pj1), hz));
                af[3] = h2u(__hmax2(__hadd2(*(const __half2*)(piR3 + k8), pj1), hz));
#pragma unroll
                for (int a = 0; a < 8; a++) mma_f16(acc[1][a], af, bf[a][0], bf[a][1]);
            }
        }

        // epilogue: per-warp partials -> sRed -> combine
#pragma unroll
        for (int am = 0; am < 2; am++) {
            float s0 = 0.f, s1 = 0.f;
#pragma unroll
            for (int a = 0; a < 8; a++) {
                int n0 = nb + 8 * a + 2 * c;
                float w0 = sW3[n0], w1 = sW3[n0 + 1];
                float bb0 = sB2[n0], bb1 = sB2[n0 + 1];
                s0 = fmaf(fmaxf(acc[am][a][0] + bb0, 0.f), w0, s0);
                s0 = fmaf(fmaxf(acc[am][a][1] + bb1, 0.f), w1, s0);
                s1 = fmaf(fmaxf(acc[am][a][2] + bb0, 0.f), w0, s1);
                s1 = fmaf(fmaxf(acc[am][a][3] + bb1, 0.f), w1, s1);
            }
            s0 += __shfl_xor_sync(0xffffffffu, s0, 1);
            s0 += __shfl_xor_sync(0xffffffffu, s0, 2);
            s1 += __shfl_xor_sync(0xffffffffu, s1, 1);
            s1 += __shfl_xor_sync(0xffffffffu, s1, 2);
            if (c == 0) {
                int m0 = mb + am * 16 + q;
                sRed[m0 * 2 + wn]       = s0;
                sRed[(m0 + 8) * 2 + wn] = s1;
            }
        }
        __syncthreads();

        if (tid < 128) {
            float s = sRed[tid * 2] + sRed[tid * 2 + 1];
            float val = tanhf(s + b3v);
            int i = i0 + (tid >> 3), j = j0 + (tid & 7);
            bool valid = (j >= i + 2) && ((j - i) != (Ndim - 1));
            outM[(b * Ndim + i) * Ndim + j] = valid ? val : 0.f;
        }

        cur = next;
        buf ^= 1;
        // top-of-loop __syncthreads (after sIdx write) guards buffer + sRed reuse
    }
}

// ---------------------------------------------------------------------------
extern "C" void kernel_launch(void* const* d_in, const int* in_sizes, int n_in,
                              void* d_out, int out_size) {
    const float* x  = (const float*)d_in[0];
    const float* W1 = (const float*)d_in[1];
    const float* b1 = (const float*)d_in[2];
    const float* W2 = (const float*)d_in[3];
    const float* b2 = (const float*)d_in[4];
    const float* W3 = (const float*)d_in[5];
    const float* b3 = (const float*)d_in[6];

    float* out = (float*)d_out;
    const int matElems  = Bdim * Ndim * Ndim;
    const int tourElems = Bdim * Ndim;
    int hasTour = (out_size >= matElems + tourElems) ? 1 : 0;
    float* outTour = out;
    float* outM    = hasTour ? (out + tourElems) : out;

    cudaMemsetAsync(outM, 0, (size_t)matElems * sizeof(float), 0);

    // reset work-stealing counter
    void* ctrPtr = nullptr;
    cudaGetSymbolAddress(&ctrPtr, g_ctr);
    cudaMemsetAsync(ctrPtr, 0, sizeof(int), 0);

    cudaFuncSetAttribute(proj_mma_kernel, cudaFuncAttributeMaxDynamicSharedMemorySize,
                         SMEM_BYTES_PROJ);
    dim3 g1(4, 4, Bdim);
    proj_mma_kernel<<<g1, 256, SMEM_BYTES_PROJ>>>(x, W1, b1, outTour, hasTour);

    cudaFuncSetAttribute(pair_mma_kernel, cudaFuncAttributeMaxDynamicSharedMemorySize,
                         SMEM_BYTES_PAIR);
    pair_mma_kernel<<<GRID_PAIR, NTHREADS, SMEM_BYTES_PAIR>>>(W2, b2, W3, b3, outM);
}

// round 13
// speedup vs baseline: 1.1120x; 1.1120x over previous
#include <cuda_runtime.h>
#include <cuda_fp16.h>
#include <math.h>
#include <stdint.h>

#define Bdim 8
#define Ndim 256
#define Ddim 128
#define K2   256

// Projections stored as fp16 (allocation-free rule -> device globals)
__device__ __half g_Pi[Bdim * Ndim * K2];   // includes b1
__device__ __half g_Pj[Bdim * Ndim * K2];

// ---------------------------------------------------------------------------
// common helpers
// ---------------------------------------------------------------------------
__device__ __forceinline__ void mma_f16(float* d, const uint32_t* a,
                                        uint32_t b0, uint32_t b1) {
    asm volatile(
        "mma.sync.aligned.m16n8k16.row.col.f32.f16.f16.f32 "
        "{%0,%1,%2,%3},{%4,%5,%6,%7},{%8,%9},{%0,%1,%2,%3};\n"
        : "+f"(d[0]), "+f"(d[1]), "+f"(d[2]), "+f"(d[3])
        : "r"(a[0]), "r"(a[1]), "r"(a[2]), "r"(a[3]), "r"(b0), "r"(b1));
}
__device__ __forceinline__ void cpa16(uint32_t dst, const void* src) {
    asm volatile("cp.async.ca.shared.global [%0], [%1], 16;"
                 :: "r"(dst), "l"(src) : "memory");
}
__device__ __forceinline__ uint32_t smem_u32(const void* p) {
    uint32_t a;
    asm("{ .reg .u64 t; cvta.to.shared.u64 t, %1; cvt.u32.u64 %0, t; }"
        : "=r"(a) : "l"(p));
    return a;
}
__device__ __forceinline__ uint32_t packh2(float a, float b) {
    __half2 h = __floats2half2_rn(a, b);
    return *(uint32_t*)&h;
}
__device__ __forceinline__ uint32_t h2u(__half2 h) { return *(uint32_t*)&h; }

// ===========================================================================
// Kernel 1: proj as fp16 tensor GEMM (R9, proven) + fused outM zeroing.
// ===========================================================================
#define PA_STR 264
#define PW_OFF_B 0
#define PA_OFF_B 65536
#define PB1_OFF_B (PA_OFF_B + 33792)
#define SMEM_BYTES_PROJ (PB1_OFF_B + 1024)

__global__ void __launch_bounds__(256, 1) proj_mma_kernel(
    const float* __restrict__ x, const float* __restrict__ W1,
    const float* __restrict__ b1, float* __restrict__ outTour, int hasTour,
    float* __restrict__ outM)
{
    extern __shared__ char smc[];
    float4* sW4 = (float4*)(smc + PW_OFF_B);
    __half* sA  = (__half*)(smc + PA_OFF_B);
    float*  sb1 = (float*)(smc + PB1_OFF_B);

    const int tid  = threadIdx.x;
    const int wid  = tid >> 5;
    const int lane = tid & 31;
    const int q = lane >> 2;
    const int c = lane & 3;
    const int nb = blockIdx.x * 128;
    const int n0 = blockIdx.y * 64;
    const int b  = blockIdx.z;

    // fused zeroing: CTA (bx,by,bz) zeros its 1/128 slice of outM (2MB total)
    {
        const int cta = (blockIdx.z * 4 + blockIdx.y) * 4 + blockIdx.x;  // 0..127
        float4* dst = (float4*)(outM) + (size_t)cta * 1024;              // 16KB per CTA
        float4 z = make_float4(0.f, 0.f, 0.f, 0.f);
#pragma unroll
        for (int u = 0; u < 4; u++) dst[u * 256 + tid] = z;
    }

    for (int idx = tid; idx < 4096; idx += 256) {
        int ln  = idx & 31;
        int wn4 = (idx >> 5) & 3;
        int gg  = (idx >> 7) & 1;
        int s   = idx >> 8;
        int cc = ln & 3, qq = ln >> 2;
        int k0 = 16 * s + 2 * cc;
        int nA = nb + wn4 * 32 + (2 * gg) * 8 + qq;
        int nB = nA + 8;
        const float* WA = (nA < 256) ? (W1 + nA) : (W1 + 256 * 256 + (nA - 256));
        const float* WB = (nB < 256) ? (W1 + nB) : (W1 + 256 * 256 + (nB - 256));
        float4 v;
        v.x = __uint_as_float(packh2(WA[k0 * 256],       WA[(k0 + 1) * 256]));
        v.y = __uint_as_float(packh2(WA[(k0 + 8) * 256], WA[(k0 + 9) * 256]));
        v.z = __uint_as_float(packh2(WB[k0 * 256],       WB[(k0 + 1) * 256]));
        v.w = __uint_as_float(packh2(WB[(k0 + 8) * 256], WB[(k0 + 9) * 256]));
        sW4[idx] = v;
    }
    if (tid < 256) sb1[tid] = b1[tid];

    for (int idx = tid; idx < 16384; idx += 256) {
        int m = idx >> 8, k = idx & 255;
        float v = (k < 128)
            ? x[((b << 8) + n0 + m) * 128 + k]
            : x[((b << 8) + ((n0 + m + 1) & 255)) * 128 + (k - 128)];
        sA[m * PA_STR + k] = __float2half(v);
    }
    __syncthreads();

    const int wm  = wid >> 2;
    const int wn4 = wid & 3;
    const float4* myW = sW4 + wn4 * 32 + lane;

    float acc[2][4][4];
#pragma unroll
    for (int am = 0; am < 2; am++)
#pragma unroll
        for (int a = 0; a < 4; a++)
#pragma unroll
            for (int e = 0; e < 4; e++) acc[am][a][e] = 0.f;

#pragma unroll 4
    for (int s = 0; s < 16; s++) {
        const int k0 = 16 * s + 2 * c;
        float4 f0 = myW[(s * 2 + 0) * 128];
        float4 f1 = myW[(s * 2 + 1) * 128];
        uint32_t bf[4][2];
        bf[0][0] = __float_as_uint(f0.x); bf[0][1] = __float_as_uint(f0.y);
        bf[1][0] = __float_as_uint(f0.z); bf[1][1] = __float_as_uint(f0.w);
        bf[2][0] = __float_as_uint(f1.x); bf[2][1] = __float_as_uint(f1.y);
        bf[3][0] = __float_as_uint(f1.z); bf[3][1] = __float_as_uint(f1.w);
#pragma unroll
        for (int am = 0; am < 2; am++) {
            const int base = wm * 32 + am * 16;
            uint32_t af[4];
            af[0] = *(const uint32_t*)(sA + (base + q) * PA_STR + k0);
            af[1] = *(const uint32_t*)(sA + (base + q + 8) * PA_STR + k0);
            af[2] = *(const uint32_t*)(sA + (base + q) * PA_STR + k0 + 8);
            af[3] = *(const uint32_t*)(sA + (base + q + 8) * PA_STR + k0 + 8);
#pragma unroll
            for (int a = 0; a < 4; a++) mma_f16(acc[am][a], af, bf[a][0], bf[a][1]);
        }
    }

#pragma unroll
    for (int am = 0; am < 2; am++) {
#pragma unroll
        for (int a = 0; a < 4; a++) {
            int col0 = nb + wn4 * 32 + a * 8 + 2 * c;
            int r0 = wm * 32 + am * 16 + q;
            float e0 = acc[am][a][0], e1 = acc[am][a][1];
            float e2 = acc[am][a][2], e3 = acc[am][a][3];
            if (col0 < 256) {
                float bb0 = sb1[col0], bb1 = sb1[col0 + 1];
                uint32_t* d0 = (uint32_t*)(g_Pi + ((b << 8) + n0 + r0) * 256 + col0);
                uint32_t* d1 = (uint32_t*)(g_Pi + ((b << 8) + n0 + r0 + 8) * 256 + col0);
                *d0 = packh2(e0 + bb0, e1 + bb1);
                *d1 = packh2(e2 + bb0, e3 + bb1);
            } else {
                int cj = col0 - 256;
                uint32_t* d0 = (uint32_t*)(g_Pj + ((b << 8) + n0 + r0) * 256 + cj);
                uint32_t* d1 = (uint32_t*)(g_Pj + ((b << 8) + n0 + r0 + 8) * 256 + cj);
                *d0 = packh2(e0, e1);
                *d1 = packh2(e2, e3);
            }
        }
    }
    if (hasTour && blockIdx.x == 0 && tid < 64)
        outTour[b * Ndim + n0 + tid] = (float)(n0 + tid);
}

// ===========================================================================
// Kernel 2: fp16 pair kernel — R11 structure (static stride, 2 CTAs/SM),
// full k-loop unroll.
// ===========================================================================
#define PIS_H 264
#define OFF_W2F_B 0                         // packed fp16 B frags: 65536 B
#define OFF_PI0_B 65536                     // 16*528 = 8448
#define OFF_PI1_B (OFF_PI0_B + 8448)        // 73984
#define OFF_PJ0_B (OFF_PI1_B + 8448)        // 82432 ; 8*528 = 4224
#define OFF_PJ1_B (OFF_PJ0_B + 4224)        // 86656
#define OFF_B2_B  (OFF_PJ1_B + 4224)        // 90880
#define OFF_W3_B  (OFF_B2_B + 512)          // 91392
#define OFF_RED_B (OFF_W3_B + 512)          // 91904 ; 256 floats = 1024 B
#define SMEM_BYTES_PAIR (OFF_RED_B + 1024)  // 92928

#define NTILES_PER_B 272                    // sum_{bi=0..15} (32 - 2*bi)
#define NTILES_TOT   (Bdim * NTILES_PER_B)  // 2176
#define GRID_PAIR    304
#define NTHREADS     256

__device__ __forceinline__ void tile_coords(int t, int& b, int& i0, int& j0) {
    b = t / NTILES_PER_B;
    int r = t - b * NTILES_PER_B;
    int bi = 0;
    while (r >= 32 - 2 * bi) { r -= 32 - 2 * bi; bi++; }
    i0 = bi * 16;
    j0 = (2 * bi + r) * 8;
}

__global__ void __launch_bounds__(NTHREADS, 2) pair_mma_kernel(
    const float* __restrict__ W2g, const float* __restrict__ b2g,
    const float* __restrict__ W3g, const float* __restrict__ b3g,
    float* __restrict__ outM)
{
    extern __shared__ char smc[];
    float4* sW2f4 = (float4*)(smc + OFF_W2F_B);
    float* sB2  = (float*)(smc + OFF_B2_B);
    float* sW3  = (float*)(smc + OFF_W3_B);
    float* sRed = (float*)(smc + OFF_RED_B);
    const uint32_t sbase = smem_u32(smc);

    const int tid  = threadIdx.x;
    const int wid  = tid >> 5;
    const int lane = tid & 31;
    const int q = lane >> 2;
    const int c = lane & 3;

    // pack fp16 B fragments (R9 layout): float4 idx ((s*4+g)*2+wn)*32+lane
    for (int idx = tid; idx < 4096; idx += NTHREADS) {
        int ln  = idx & 31;
        int wnn = (idx >> 5) & 1;
        int g   = (idx >> 6) & 3;
        int s   = idx >> 8;
        int cc  = ln & 3, qq = ln >> 2;
        int k0  = 16 * s + 2 * cc;
        int n0  = 64 * wnn + 16 * g + qq;
        int n1  = n0 + 8;
        float4 v;
        v.x = __uint_as_float(packh2(W2g[k0 * 128 + n0],       W2g[(k0 + 1) * 128 + n0]));
        v.y = __uint_as_float(packh2(W2g[(k0 + 8) * 128 + n0], W2g[(k0 + 9) * 128 + n0]));
        v.z = __uint_as_float(packh2(W2g[k0 * 128 + n1],       W2g[(k0 + 1) * 128 + n1]));
        v.w = __uint_as_float(packh2(W2g[(k0 + 8) * 128 + n1], W2g[(k0 + 9) * 128 + n1]));
        sW2f4[idx] = v;
    }
    if (tid < 128) { sB2[tid] = b2g[tid]; sW3[tid] = W3g[tid]; }
    const float b3v = b3g[0];

    const int wm = wid >> 1;          // 0..3 -> rows 32*wm
    const int wn = wid & 1;           // 0..1 -> cols 64*wn
    const int mb = wm * 32;
    const int nb = wn * 64;
    const float4* myB = sW2f4 + wn * 32 + lane;

    // prefetch first tile
    {
        int b, i0, j0;
        tile_coords(blockIdx.x, b, i0, j0);
        const __half* gPi = g_Pi + (size_t)(b * Ndim + i0) * K2;
        const __half* gPj = g_Pj + (size_t)(b * Ndim + j0) * K2;
#pragma unroll
        for (int u = 0; u < 2; u++) {
            int idx = u * NTHREADS + tid;
            int row = idx >> 5, ch = idx & 31;
            cpa16(sbase + OFF_PI0_B + row * 528 + ch * 16, gPi + row * 256 + ch * 8);
        }
        {
            int row = tid >> 5, ch = tid & 31;
            cpa16(sbase + OFF_PJ0_B + row * 528 + ch * 16, gPj + row * 256 + ch * 8);
        }
        asm volatile("cp.async.commit_group;" ::: "memory");
    }

    const __half2 hz = __float2half2_rn(0.f);

    int cnt = 0;
    for (int t = blockIdx.x; t < NTILES_TOT; t += GRID_PAIR, cnt++) {
        const int buf = cnt & 1;

        if (t + GRID_PAIR < NTILES_TOT) {
            int b, i0, j0;
            tile_coords(t + GRID_PAIR, b, i0, j0);
            const __half* gPi = g_Pi + (size_t)(b * Ndim + i0) * K2;
            const __half* gPj = g_Pj + (size_t)(b * Ndim + j0) * K2;
            const int piO = buf ? OFF_PI0_B : OFF_PI1_B;
            const int pjO = buf ? OFF_PJ0_B : OFF_PJ1_B;
#pragma unroll
            for (int u = 0; u < 2; u++) {
                int idx = u * NTHREADS + tid;
                int row = idx >> 5, ch = idx & 31;
                cpa16(sbase + piO + row * 528 + ch * 16, gPi + row * 256 + ch * 8);
            }
            {
                int row = tid >> 5, ch = tid & 31;
                cpa16(sbase + pjO + row * 528 + ch * 16, gPj + row * 256 + ch * 8);
            }
            asm volatile("cp.async.commit_group;" ::: "memory");
            asm volatile("cp.async.wait_group 1;" ::: "memory");
        } else {
            asm volatile("cp.async.wait_group 0;" ::: "memory");
        }
        __syncthreads();

        int b, i0, j0;
        tile_coords(t, b, i0, j0);

        const __half* sPi = (const __half*)(smc + (buf ? OFF_PI1_B : OFF_PI0_B));
        const __half* sPj = (const __half*)(smc + (buf ? OFF_PJ1_B : OFF_PJ0_B));
        const __half* piR0 = sPi + ((mb >> 3) + 0) * PIS_H;
        const __half* piR1 = sPi + ((mb >> 3) + 1) * PIS_H;
        const __half* piR2 = sPi + ((mb >> 3) + 2) * PIS_H;
        const __half* piR3 = sPi + ((mb >> 3) + 3) * PIS_H;
        const __half* pjR  = sPj + q * PIS_H;

        float acc[2][8][4];
#pragma unroll
        for (int am = 0; am < 2; am++)
#pragma unroll
            for (int a = 0; a < 8; a++)
#pragma unroll
                for (int e = 0; e < 4; e++) acc[am][a][e] = 0.f;

#pragma unroll
        for (int s = 0; s < 16; s++) {
            const int k0 = 16 * s + 2 * c;
            const int k8 = k0 + 8;

            float4 f0 = myB[(s * 4 + 0) * 64];
            float4 f1 = myB[(s * 4 + 1) * 64];
            float4 f2 = myB[(s * 4 + 2) * 64];
            float4 f3 = myB[(s * 4 + 3) * 64];
            uint32_t bf[8][2];
            bf[0][0] = __float_as_uint(f0.x); bf[0][1] = __float_as_uint(f0.y);
            bf[1][0] = __float_as_uint(f0.z); bf[1][1] = __float_as_uint(f0.w);
            bf[2][0] = __float_as_uint(f1.x); bf[2][1] = __float_as_uint(f1.y);
            bf[3][0] = __float_as_uint(f1.z); bf[3][1] = __float_as_uint(f1.w);
            bf[4][0] = __float_as_uint(f2.x); bf[4][1] = __float_as_uint(f2.y);
            bf[5][0] = __float_as_uint(f2.z); bf[5][1] = __float_as_uint(f2.w);
            bf[6][0] = __float_as_uint(f3.x); bf[6][1] = __float_as_uint(f3.y);
            bf[7][0] = __float_as_uint(f3.z); bf[7][1] = __float_as_uint(f3.w);

            const __half2 pj0 = *(const __half2*)(pjR + k0);
            const __half2 pj1 = *(const __half2*)(pjR + k8);

            {   // M-atom 0: rows mb+q, mb+q+8
                uint32_t af[4];
                af[0] = h2u(__hmax2(__hadd2(*(const __half2*)(piR0 + k0), pj0), hz));
                af[1] = h2u(__hmax2(__hadd2(*(const __half2*)(piR1 + k0), pj0), hz));
                af[2] = h2u(__hmax2(__hadd2(*(const __half2*)(piR0 + k8), pj1), hz));
                af[3] = h2u(__hmax2(__hadd2(*(const __half2*)(piR1 + k8), pj1), hz));
#pragma unroll
                for (int a = 0; a < 8; a++) mma_f16(acc[0][a], af, bf[a][0], bf[a][1]);
            }
            {   // M-atom 1: rows mb+q+16, mb+q+24
                uint32_t af[4];
                af[0] = h2u(__hmax2(__hadd2(*(const __half2*)(piR2 + k0), pj0), hz));
                af[1] = h2u(__hmax2(__hadd2(*(const __half2*)(piR3 + k0), pj0), hz));
                af[2] = h2u(__hmax2(__hadd2(*(const __half2*)(piR2 + k8), pj1), hz));
                af[3] = h2u(__hmax2(__hadd2(*(const __half2*)(piR3 + k8), pj1), hz));
#pragma unroll
                for (int a = 0; a < 8; a++) mma_f16(acc[1][a], af, bf[a][0], bf[a][1]);
            }
        }

        // epilogue: per-warp partials -> sRed -> combine
#pragma unroll
        for (int am = 0; am < 2; am++) {
            float s0 = 0.f, s1 = 0.f;
#pragma unroll
            for (int a = 0; a < 8; a++) {
                int n0 = nb + 8 * a + 2 * c;
                float w0 = sW3[n0], w1 = sW3[n0 + 1];
                float bb0 = sB2[n0], bb1 = sB2[n0 + 1];
                s0 = fmaf(fmaxf(acc[am][a][0] + bb0, 0.f), w0, s0);
                s0 = fmaf(fmaxf(acc[am][a][1] + bb1, 0.f), w1, s0);
                s1 = fmaf(fmaxf(acc[am][a][2] + bb0, 0.f), w0, s1);
                s1 = fmaf(fmaxf(acc[am][a][3] + bb1, 0.f), w1, s1);
            }
            s0 += __shfl_xor_sync(0xffffffffu, s0, 1);
            s0 += __shfl_xor_sync(0xffffffffu, s0, 2);
            s1 += __shfl_xor_sync(0xffffffffu, s1, 1);
            s1 += __shfl_xor_sync(0xffffffffu, s1, 2);
            if (c == 0) {
                int m0 = mb + am * 16 + q;
                sRed[m0 * 2 + wn]       = s0;
                sRed[(m0 + 8) * 2 + wn] = s1;
            }
        }
        __syncthreads();

        if (tid < 128) {
            float s = sRed[tid * 2] + sRed[tid * 2 + 1];
            float val = tanhf(s + b3v);
            int i = i0 + (tid >> 3), j = j0 + (tid & 7);
            bool valid = (j >= i + 2) && ((j - i) != (Ndim - 1));
            outM[(b * Ndim + i) * Ndim + j] = valid ? val : 0.f;
        }
        // next-iteration post-wait __syncthreads guards sRed + buffer reuse
    }
}

// ---------------------------------------------------------------------------
extern "C" void kernel_launch(void* const* d_in, const int* in_sizes, int n_in,
                              void* d_out, int out_size) {
    const float* x  = (const float*)d_in[0];
    const float* W1 = (const float*)d_in[1];
    const float* b1 = (const float*)d_in[2];
    const float* W2 = (const float*)d_in[3];
    const float* b2 = (const float*)d_in[4];
    const float* W3 = (const float*)d_in[5];
    const float* b3 = (const float*)d_in[6];

    float* out = (float*)d_out;
    const int matElems  = Bdim * Ndim * Ndim;
    const int tourElems = Bdim * Ndim;
    int hasTour = (out_size >= matElems + tourElems) ? 1 : 0;
    float* outTour = out;
    float* outM    = hasTour ? (out + tourElems) : out;

    cudaFuncSetAttribute(proj_mma_kernel, cudaFuncAttributeMaxDynamicSharedMemorySize,
                         SMEM_BYTES_PROJ);
    dim3 g1(4, 4, Bdim);
    proj_mma_kernel<<<g1, 256, SMEM_BYTES_PROJ>>>(x, W1, b1, outTour, hasTour, outM);

    cudaFuncSetAttribute(pair_mma_kernel, cudaFuncAttributeMaxDynamicSharedMemorySize,
                         SMEM_BYTES_PAIR);
    pair_mma_kernel<<<GRID_PAIR, NTHREADS, SMEM_BYTES_PAIR>>>(W2, b2, W3, b3, outM);
}

// round 17
// speedup vs baseline: 1.1855x; 1.0661x over previous
#include <cuda_runtime.h>
#include <cuda_fp16.h>
#include <math.h>
#include <stdint.h>

#define Bdim 8
#define Ndim 256
#define Ddim 128
#define K2   256

// Device globals (allocation-free rule)
__device__ __half g_Pi[Bdim * Ndim * K2];   // includes b1
__device__ __half g_Pj[Bdim * Ndim * K2];
__device__ float4 g_W2f[4096];              // pre-packed pair-B fragments (64 KB)

// ---------------------------------------------------------------------------
// helpers
// ---------------------------------------------------------------------------
__device__ __forceinline__ void mma_f16(float* d, const uint32_t* a,
                                        uint32_t b0, uint32_t b1) {
    asm volatile(
        "mma.sync.aligned.m16n8k16.row.col.f32.f16.f16.f32 "
        "{%0,%1,%2,%3},{%4,%5,%6,%7},{%8,%9},{%0,%1,%2,%3};\n"
        : "+f"(d[0]), "+f"(d[1]), "+f"(d[2]), "+f"(d[3])
        : "r"(a[0]), "r"(a[1]), "r"(a[2]), "r"(a[3]), "r"(b0), "r"(b1));
}
__device__ __forceinline__ void cpa16(uint32_t dst, const void* src) {
    asm volatile("cp.async.ca.shared.global [%0], [%1], 16;"
                 :: "r"(dst), "l"(src) : "memory");
}
__device__ __forceinline__ uint32_t smem_u32(const void* p) {
    uint32_t a;
    asm("{ .reg .u64 t; cvta.to.shared.u64 t, %1; cvt.u32.u64 %0, t; }"
        : "=r"(a) : "l"(p));
    return a;
}
__device__ __forceinline__ uint32_t packh2(float a, float b) {
    __half2 h = __floats2half2_rn(a, b);
    return *(uint32_t*)&h;
}
__device__ __forceinline__ uint32_t h2u(__half2 h) { return *(uint32_t*)&h; }

// ===========================================================================
// Kernel 1: proj as fp16 tensor GEMM (R13/R16, proven) + fused outM zeroing
// + pair-B fragment pre-packing (ordered via kernel boundary).
// ===========================================================================
#define PA_STR 264
#define PW_OFF_B 0
#define PA_OFF_B 65536
#define PB1_OFF_B (PA_OFF_B + 33792)
#define SMEM_BYTES_PROJ (PB1_OFF_B + 1024)

__global__ void __launch_bounds__(256, 1) proj_mma_kernel(
    const float* __restrict__ x, const float* __restrict__ W1,
    const float* __restrict__ b1, const float* __restrict__ W2g,
    float* __restrict__ outTour, int hasTour, float* __restrict__ outM)
{
    extern __shared__ char smc[];
    float4* sW4 = (float4*)(smc + PW_OFF_B);
    __half* sA  = (__half*)(smc + PA_OFF_B);
    float*  sb1 = (float*)(smc + PB1_OFF_B);

    const int tid  = threadIdx.x;
    const int wid  = tid >> 5;
    const int lane = tid & 31;
    const int q = lane >> 2;
    const int c = lane & 3;
    const int nb = blockIdx.x * 128;
    const int n0 = blockIdx.y * 64;
    const int b  = blockIdx.z;
    const int cta = (blockIdx.z * 4 + blockIdx.y) * 4 + blockIdx.x;  // 0..127

    // fused zeroing: this CTA zeros its 16KB slice of outM
    {
        float4* dst = (float4*)(outM) + (size_t)cta * 1024;
        float4 z = make_float4(0.f, 0.f, 0.f, 0.f);
#pragma unroll
        for (int u = 0; u < 4; u++) dst[u * 256 + tid] = z;
    }

    // pre-pack this CTA's 32 entries of the pair-B fragment array
    if (tid < 32) {
        int idx = cta * 32 + tid;
        int ln  = idx & 31;
        int wnn = (idx >> 5) & 1;
        int g   = (idx >> 6) & 3;
        int s   = idx >> 8;
        int cc  = ln & 3, qq = ln >> 2;
        int k0  = 16 * s + 2 * cc;
        int pn0 = 64 * wnn + 16 * g + qq;
        int pn1 = pn0 + 8;
        float4 v;
        v.x = __uint_as_float(packh2(W2g[k0 * 128 + pn0],       W2g[(k0 + 1) * 128 + pn0]));
        v.y = __uint_as_float(packh2(W2g[(k0 + 8) * 128 + pn0], W2g[(k0 + 9) * 128 + pn0]));
        v.z = __uint_as_float(packh2(W2g[k0 * 128 + pn1],       W2g[(k0 + 1) * 128 + pn1]));
        v.w = __uint_as_float(packh2(W2g[(k0 + 8) * 128 + pn1], W2g[(k0 + 9) * 128 + pn1]));
        g_W2f[idx] = v;
    }

    // pack proj W fragments (fp16) into smem
    for (int idx = tid; idx < 4096; idx += 256) {
        int ln  = idx & 31;
        int wn4 = (idx >> 5) & 3;
        int gg  = (idx >> 7) & 1;
        int s   = idx >> 8;
        int cc = ln & 3, qq = ln >> 2;
        int k0 = 16 * s + 2 * cc;
        int nA = nb + wn4 * 32 + (2 * gg) * 8 + qq;
        int nB = nA + 8;
        const float* WA = (nA < 256) ? (W1 + nA) : (W1 + 256 * 256 + (nA - 256));
        const float* WB = (nB < 256) ? (W1 + nB) : (W1 + 256 * 256 + (nB - 256));
        float4 v;
        v.x = __uint_as_float(packh2(WA[k0 * 256],       WA[(k0 + 1) * 256]));
        v.y = __uint_as_float(packh2(WA[(k0 + 8) * 256], WA[(k0 + 9) * 256]));
        v.z = __uint_as_float(packh2(WB[k0 * 256],       WB[(k0 + 1) * 256]));
        v.w = __uint_as_float(packh2(WB[(k0 + 8) * 256], WB[(k0 + 9) * 256]));
        sW4[idx] = v;
    }
    sb1[tid] = b1[tid];

    for (int idx = tid; idx < 16384; idx += 256) {
        int m = idx >> 8, k = idx & 255;
        float v = (k < 128)
            ? x[((b << 8) + n0 + m) * 128 + k]
            : x[((b << 8) + ((n0 + m + 1) & 255)) * 128 + (k - 128)];
        sA[m * PA_STR + k] = __float2half(v);
    }
    __syncthreads();

    const int wm  = wid >> 2;
    const int wn4 = wid & 3;
    const float4* myW = sW4 + wn4 * 32 + lane;

    float acc[2][4][4];
#pragma unroll
    for (int am = 0; am < 2; am++)
#pragma unroll
        for (int a = 0; a < 4; a++)
#pragma unroll
            for (int e = 0; e < 4; e++) acc[am][a][e] = 0.f;

#pragma unroll 4
    for (int s = 0; s < 16; s++) {
        const int k0 = 16 * s + 2 * c;
        float4 f0 = myW[(s * 2 + 0) * 128];
        float4 f1 = myW[(s * 2 + 1) * 128];
        uint32_t bf[4][2];
        bf[0][0] = __float_as_uint(f0.x); bf[0][1] = __float_as_uint(f0.y);
        bf[1][0] = __float_as_uint(f0.z); bf[1][1] = __float_as_uint(f0.w);
        bf[2][0] = __float_as_uint(f1.x); bf[2][1] = __float_as_uint(f1.y);
        bf[3][0] = __float_as_uint(f1.z); bf[3][1] = __float_as_uint(f1.w);
#pragma unroll
        for (int am = 0; am < 2; am++) {
            const int base = wm * 32 + am * 16;
            uint32_t af[4];
            af[0] = *(const uint32_t*)(sA + (base + q) * PA_STR + k0);
            af[1] = *(const uint32_t*)(sA + (base + q + 8) * PA_STR + k0);
            af[2] = *(const uint32_t*)(sA + (base + q) * PA_STR + k0 + 8);
            af[3] = *(const uint32_t*)(sA + (base + q + 8) * PA_STR + k0 + 8);
#pragma unroll
            for (int a = 0; a < 4; a++) mma_f16(acc[am][a], af, bf[a][0], bf[a][1]);
        }
    }

#pragma unroll
    for (int am = 0; am < 2; am++) {
#pragma unroll
        for (int a = 0; a < 4; a++) {
            int col0 = nb + wn4 * 32 + a * 8 + 2 * c;
            int r0 = wm * 32 + am * 16 + q;
            float e0 = acc[am][a][0], e1 = acc[am][a][1];
            float e2 = acc[am][a][2], e3 = acc[am][a][3];
            if (col0 < 256) {
                float bb0 = sb1[col0], bb1 = sb1[col0 + 1];
                uint32_t* d0 = (uint32_t*)(g_Pi + ((b << 8) + n0 + r0) * 256 + col0);
                uint32_t* d1 = (uint32_t*)(g_Pi + ((b << 8) + n0 + r0 + 8) * 256 + col0);
                *d0 = packh2(e0 + bb0, e1 + bb1);
                *d1 = packh2(e2 + bb0, e3 + bb1);
            } else {
                int cj = col0 - 256;
                uint32_t* d0 = (uint32_t*)(g_Pj + ((b << 8) + n0 + r0) * 256 + cj);
                uint32_t* d1 = (uint32_t*)(g_Pj + ((b << 8) + n0 + r0 + 8) * 256 + cj);
                *d0 = packh2(e0, e1);
                *d1 = packh2(e2, e3);
            }
        }
    }
    if (hasTour && blockIdx.x == 0 && tid < 64)
        outTour[b * Ndim + n0 + tid] = (float)(n0 + tid);
}

// ===========================================================================
// Kernel 2: fp16 pair kernel — triple-buffered Pi/Pj, prefetch issued AFTER
// the per-tile __syncthreads (race-free by construction), one CTA barrier
// per tile, named-barrier epilogue, pre-packed B via cp.async.
// ===========================================================================
#define PIS_H 264
#define PBUF_STRIDE 12672                   // Pi (8448) + Pj (4224) per buffer
#define OFF_W2F_B 0                         // packed fp16 B frags: 65536 B
#define OFF_P0_B  65536                     // 3 buffers
#define OFF_B2_B  (OFF_P0_B + 3 * PBUF_STRIDE)   // 103552
#define OFF_W3_B  (OFF_B2_B + 512)          // 104064
#define OFF_RED_B (OFF_W3_B + 512)          // 104576 ; 256 floats = 1024 B
#define SMEM_BYTES_PAIR (OFF_RED_B + 1024)  // 105600

#define NTILES_PER_B 272                    // sum_{bi=0..15} (32 - 2*bi)
#define NTILES_TOT   (Bdim * NTILES_PER_B)  // 2176
#define GRID_PAIR    304
#define NTHREADS     256

__device__ __forceinline__ void tile_coords(int t, int& b, int& i0, int& j0) {
    b = t / NTILES_PER_B;
    int r = t - b * NTILES_PER_B;
    int bi = 0;
    while (r >= 32 - 2 * bi) { r -= 32 - 2 * bi; bi++; }
    i0 = bi * 16;
    j0 = (2 * bi + r) * 8;
}

__global__ void __launch_bounds__(NTHREADS, 2) pair_mma_kernel(
    const float* __restrict__ b2g, const float* __restrict__ W3g,
    const float* __restrict__ b3g, float* __restrict__ outM)
{
    extern __shared__ char smc[];
    float4* sW2f4 = (float4*)(smc + OFF_W2F_B);
    float* sB2  = (float*)(smc + OFF_B2_B);
    float* sW3  = (float*)(smc + OFF_W3_B);
    float* sRed = (float*)(smc + OFF_RED_B);
    const uint32_t sbase = smem_u32(smc);

    const int tid  = threadIdx.x;
    const int wid  = tid >> 5;
    const int lane = tid & 31;
    const int q = lane >> 2;
    const int c = lane & 3;

    // per-thread staging roles (constant across tiles)
    const int piRowA = tid >> 5,            piChA = tid & 31;   // Pi chunks 0..511 (x2)
    const int pjRow  = tid >> 5,            pjCh  = tid & 31;   // Pj chunks 0..255

    // load pre-packed B fragments via cp.async (16 x 16B per thread) — group 0
#pragma unroll
    for (int u = 0; u < 16; u++) {
        int idx = u * NTHREADS + tid;
        cpa16(sbase + OFF_W2F_B + idx * 16, g_W2f + idx);
    }
    // prefetch tile(cta) into buffer 0 — same group
    {
        int b, i0, j0;
        tile_coords(blockIdx.x, b, i0, j0);
        const __half* gPi = g_Pi + (size_t)(b * Ndim + i0) * K2;
        const __half* gPj = g_Pj + (size_t)(b * Ndim + j0) * K2;
#pragma unroll
        for (int u = 0; u < 2; u++) {
            int row = (u * NTHREADS + tid) >> 5, ch = (u * NTHREADS + tid) & 31;
            cpa16(sbase + OFF_P0_B + row * 528 + ch * 16, gPi + row * 256 + ch * 8);
        }
        cpa16(sbase + OFF_P0_B + 8448 + pjRow * 528 + pjCh * 16, gPj + pjRow * 256 + pjCh * 8);
        asm volatile("cp.async.commit_group;" ::: "memory");
    }
    // prefetch tile(cta + GRID) into buffer 1 — group 1 (always exists: 607 < 2176)
    {
        int b, i0, j0;
        tile_coords(blockIdx.x + GRID_PAIR, b, i0, j0);
        const __half* gPi = g_Pi + (size_t)(b * Ndim + i0) * K2;
        const __half* gPj = g_Pj + (size_t)(b * Ndim + j0) * K2;
#pragma unroll
        for (int u = 0; u < 2; u++) {
            int row = (u * NTHREADS + tid) >> 5, ch = (u * NTHREADS + tid) & 31;
            cpa16(sbase + OFF_P0_B + PBUF_STRIDE + row * 528 + ch * 16, gPi + row * 256 + ch * 8);
        }
        cpa16(sbase + OFF_P0_B + PBUF_STRIDE + 8448 + pjRow * 528 + pjCh * 16,
              gPj + pjRow * 256 + pjCh * 8);
        asm volatile("cp.async.commit_group;" ::: "memory");
    }

    if (tid < 128) { sB2[tid] = b2g[tid]; sW3[tid] = W3g[tid]; }
    const float b3v = b3g[0];

    const int wm = wid >> 1;          // 0..3 -> rows 32*wm
    const int wn = wid & 1;           // 0..1 -> cols 64*wn
    const int mb = wm * 32;
    const int nb = wn * 64;
    const float4* myB = sW2f4 + wn * 32 + lane;

    const __half2 hz = __float2half2_rn(0.f);

    int bc = 0;   // buffer index of current tile (cnt % 3)
    for (int t = blockIdx.x; t < NTILES_TOT; t += GRID_PAIR) {
        // wait for current tile's group (keep <=1 groups outstanding), then sync
        asm volatile("cp.async.wait_group 1;" ::: "memory");
        __syncthreads();
        // ^ after this sync: current tile (buf bc) visible to all threads, AND
        //   every warp has finished the previous tile's compute -> buffer
        //   bp = (bc+2)%3 (read two tiles ago) is free to overwrite.

        // prefetch tile t + 2*GRID into buffer bp (issued after the sync)
        int bp = bc + 2; if (bp >= 3) bp -= 3;
        if (t + 2 * GRID_PAIR < NTILES_TOT) {
            int b2_, i0_, j0_;
            tile_coords(t + 2 * GRID_PAIR, b2_, i0_, j0_);
            const __half* gPi = g_Pi + (size_t)(b2_ * Ndim + i0_) * K2;
            const __half* gPj = g_Pj + (size_t)(b2_ * Ndim + j0_) * K2;
            const uint32_t pb = sbase + OFF_P0_B + bp * PBUF_STRIDE;
#pragma unroll
            for (int u = 0; u < 2; u++) {
                int row = (u * NTHREADS + tid) >> 5, ch = (u * NTHREADS + tid) & 31;
                cpa16(pb + row * 528 + ch * 16, gPi + row * 256 + ch * 8);
            }
            cpa16(pb + 8448 + pjRow * 528 + pjCh * 16, gPj + pjRow * 256 + pjCh * 8);
        }
        asm volatile("cp.async.commit_group;" ::: "memory");  // (possibly empty)

        int b, i0, j0;
        tile_coords(t, b, i0, j0);

        const __half* sPi = (const __half*)(smc + OFF_P0_B + bc * PBUF_STRIDE);
        const __half* sPj = sPi + 8448 / 2;
        const __half* piR0 = sPi + ((mb >> 3) + 0) * PIS_H;
        const __half* piR1 = sPi + ((mb >> 3) + 1) * PIS_H;
        const __half* piR2 = sPi + ((mb >> 3) + 2) * PIS_H;
        const __half* piR3 = sPi + ((mb >> 3) + 3) * PIS_H;
        const __half* pjR  = sPj + q * PIS_H;

        float acc[2][8][4];
#pragma unroll
        for (int am = 0; am < 2; am++)
#pragma unroll
            for (int a = 0; a < 8; a++)
#pragma unroll
                for (int e = 0; e < 4; e++) acc[am][a][e] = 0.f;

#pragma unroll
        for (int s = 0; s < 16; s++) {
            const int k0 = 16 * s + 2 * c;
            const int k8 = k0 + 8;

            float4 f0 = myB[(s * 4 + 0) * 64];
            float4 f1 = myB[(s * 4 + 1) * 64];
            float4 f2 = myB[(s * 4 + 2) * 64];
            float4 f3 = myB[(s * 4 + 3) * 64];
            uint32_t bf[8][2];
            bf[0][0] = __float_as_uint(f0.x); bf[0][1] = __float_as_uint(f0.y);
            bf[1][0] = __float_as_uint(f0.z); bf[1][1] = __float_as_uint(f0.w);
            bf[2][0] = __float_as_uint(f1.x); bf[2][1] = __float_as_uint(f1.y);
            bf[3][0] = __float_as_uint(f1.z); bf[3][1] = __float_as_uint(f1.w);
            bf[4][0] = __float_as_uint(f2.x); bf[4][1] = __float_as_uint(f2.y);
            bf[5][0] = __float_as_uint(f2.z); bf[5][1] = __float_as_uint(f2.w);
            bf[6][0] = __float_as_uint(f3.x); bf[6][1] = __float_as_uint(f3.y);
            bf[7][0] = __float_as_uint(f3.z); bf[7][1] = __float_as_uint(f3.w);

            const __half2 pj0 = *(const __half2*)(pjR + k0);
            const __half2 pj1 = *(const __half2*)(pjR + k8);

            {   // M-atom 0: rows mb+q, mb+q+8
                uint32_t af[4];
                af[0] = h2u(__hmax2(__hadd2(*(const __half2*)(piR0 + k0), pj0), hz));
                af[1] = h2u(__hmax2(__hadd2(*(const __half2*)(piR1 + k0), pj0), hz));
                af[2] = h2u(__hmax2(__hadd2(*(const __half2*)(piR0 + k8), pj1), hz));
                af[3] = h2u(__hmax2(__hadd2(*(const __half2*)(piR1 + k8), pj1), hz));
#pragma unroll
                for (int a = 0; a < 8; a++) mma_f16(acc[0][a], af, bf[a][0], bf[a][1]);
            }
            {   // M-atom 1: rows mb+q+16, mb+q+24
                uint32_t af[4];
                af[0] = h2u(__hmax2(__hadd2(*(const __half2*)(piR2 + k0), pj0), hz));
                af[1] = h2u(__hmax2(__hadd2(*(const __half2*)(piR3 + k0), pj0), hz));
                af[2] = h2u(__hmax2(__hadd2(*(const __half2*)(piR2 + k8), pj1), hz));
                af[3] = h2u(__hmax2(__hadd2(*(const __half2*)(piR3 + k8), pj1), hz));
#pragma unroll
                for (int a = 0; a < 8; a++) mma_f16(acc[1][a], af, bf[a][0], bf[a][1]);
            }
        }

        // epilogue: per-warp partials -> sRed -> named-barrier pair combine.
        // sRed reuse across tiles is guarded by the next iteration's
        // __syncthreads (writers of tile t+1 pass it only after ALL threads
        // — including this tile's readers — arrive).
#pragma unroll
        for (int am = 0; am < 2; am++) {
            float s0 = 0.f, s1 = 0.f;
#pragma unroll
            for (int a = 0; a < 8; a++) {
                int n0 = nb + 8 * a + 2 * c;
                float w0 = sW3[n0], w1 = sW3[n0 + 1];
                float bb0 = sB2[n0], bb1 = sB2[n0 + 1];
                s0 = fmaf(fmaxf(acc[am][a][0] + bb0, 0.f), w0, s0);
                s0 = fmaf(fmaxf(acc[am][a][1] + bb1, 0.f), w1, s0);
                s1 = fmaf(fmaxf(acc[am][a][2] + bb0, 0.f), w0, s1);
                s1 = fmaf(fmaxf(acc[am][a][3] + bb1, 0.f), w1, s1);
            }
            s0 += __shfl_xor_sync(0xffffffffu, s0, 1);
            s0 += __shfl_xor_sync(0xffffffffu, s0, 2);
            s1 += __shfl_xor_sync(0xffffffffu, s1, 1);
            s1 += __shfl_xor_sync(0xffffffffu, s1, 2);
            if (c == 0) {
                int m0 = mb + am * 16 + q;
                sRed[m0 * 2 + wn]       = s0;
                sRed[(m0 + 8) * 2 + wn] = s1;
            }
        }
        // sync only the 2 warps sharing this wm (barrier ids 1..4)
        asm volatile("bar.sync %0, 64;" :: "r"(1 + wm) : "memory");

        if (wn == 0) {   // warp 2*wm finalizes its 32 rows
            int p = mb + lane;
            float s = sRed[p * 2] + sRed[p * 2 + 1];
            float val = tanhf(s + b3v);
            int i = i0 + (p >> 3), j = j0 + (p & 7);
            bool valid = (j >= i + 2) && ((j - i) != (Ndim - 1));
            outM[(b * Ndim + i) * Ndim + j] = valid ? val : 0.f;
        }

        bc = bc + 1; if (bc >= 3) bc = 0;
    }
}

// ---------------------------------------------------------------------------
extern "C" void kernel_launch(void* const* d_in, const int* in_sizes, int n_in,
                              void* d_out, int out_size) {
    const float* x  = (const float*)d_in[0];
    const float* W1 = (const float*)d_in[1];
    const float* b1 = (const float*)d_in[2];
    const float* W2 = (const float*)d_in[3];
    const float* b2 = (const float*)d_in[4];
    const float* W3 = (const float*)d_in[5];
    const float* b3 = (const float*)d_in[6];

    float* out = (float*)d_out;
    const int matElems  = Bdim * Ndim * Ndim;
    const int tourElems = Bdim * Ndim;
    int hasTour = (out_size >= matElems + tourElems) ? 1 : 0;
    float* outTour = out;
    float* outM    = hasTour ? (out + tourElems) : out;

    cudaFuncSetAttribute(proj_mma_kernel, cudaFuncAttributeMaxDynamicSharedMemorySize,
                         SMEM_BYTES_PROJ);
    dim3 g1(4, 4, Bdim);
    proj_mma_kernel<<<g1, 256, SMEM_BYTES_PROJ>>>(x, W1, b1, W2, outTour, hasTour, outM);

    cudaFuncSetAttribute(pair_mma_kernel, cudaFuncAttributeMaxDynamicSharedMemorySize,
                         SMEM_BYTES_PAIR);
    pair_mma_kernel<<<GRID_PAIR, NTHREADS, SMEM_BYTES_PAIR>>>(b2, W3, b3, outM);
}